// round 6
// baseline (speedup 1.0000x reference)
#include <cuda_runtime.h>

#define BB 4096
#define TT 400
#define CC 42
#define HH 16
#define SCALE 2.885390081777927f  // 2 * log2(e), folded into U, recurrent weights, bias1

// g_U[pair(2048)][t(400)][i(16)] as f32x2 (lo = even batch, hi = odd batch), pre-scaled.
__device__ __align__(16) unsigned long long g_U[2048ull * TT * 16];

// ---------- f32x2 helpers ----------
__device__ __forceinline__ unsigned long long pk2(float lo, float hi) {
    unsigned long long r;
    asm("mov.b64 %0, {%1, %2};" : "=l"(r) : "f"(lo), "f"(hi));
    return r;
}
__device__ __forceinline__ void up2(unsigned long long v, float& a, float& b) {
    asm("mov.b64 {%0, %1}, %2;" : "=f"(a), "=f"(b) : "l"(v));
}
__device__ __forceinline__ unsigned long long fma2(unsigned long long a, unsigned long long b,
                                                   unsigned long long c) {
    unsigned long long d;
    asm("fma.rn.f32x2 %0, %1, %2, %3;" : "=l"(d) : "l"(a), "l"(b), "l"(c));
    return d;
}
__device__ __forceinline__ unsigned long long add2(unsigned long long a, unsigned long long b) {
    unsigned long long d;
    asm("add.rn.f32x2 %0, %1, %2;" : "=l"(d) : "l"(a), "l"(b));
    return d;
}
// tanh with pre-scaled argument: z = 2*log2(e)*x  ->  tanh(x) = 1 - 2/(1+2^z)
__device__ __forceinline__ float tanh_pre(float z) {
    float e, r;
    asm("ex2.approx.f32 %0, %1;" : "=f"(e) : "f"(z));
    asm("rcp.approx.f32 %0, %1;" : "=f"(r) : "f"(e + 1.0f));
    return fmaf(-2.0f, r, 1.0f);
}
__device__ __forceinline__ unsigned long long tanh2_pre(unsigned long long z) {
    float a, b;
    up2(z, a, b);
    return pk2(tanh_pre(a), tanh_pre(b));
}

// ---------- Kernel A: U[p][t][:] = SCALE*(bias0 + W_ih0 @ x_t)  (unchanged, best known) ----------
__global__ void __launch_bounds__(128) kA(const float* __restrict__ x,
                                          const float* __restrict__ Wih0,
                                          const float* __restrict__ bih0,
                                          const float* __restrict__ bhh0) {
    __shared__ __align__(16) unsigned long long swd[CC][HH];
    __shared__ unsigned long long sb[HH];
    __shared__ __align__(16) unsigned long long sstage[128][18];

    int tid = threadIdx.x;
    for (int k = tid; k < CC * HH; k += 128) {
        int c = k >> 4, i = k & 15;
        float wv = SCALE * Wih0[i * CC + c];
        swd[c][i] = pk2(wv, wv);
    }
    if (tid < HH) {
        float b = SCALE * (bih0[tid] + bhh0[tid]);
        sb[tid] = pk2(b, b);
    }
    __syncthreads();

    int tc = blockIdx.x;    // 0..24
    int bblk = blockIdx.y;  // 0..255
    int w = tid >> 5, lane = tid & 31;
    int s = lane >> 4, tl = lane & 15;
    int ploc = w * 2 + s;
    int p = bblk * 8 + ploc;
    int t = tc * 16 + tl;

    const float* xb0 = x + (size_t)(2 * p) * (CC * TT) + t;
    const float* xb1 = xb0 + (CC * TT);

    unsigned long long u[16];
#pragma unroll
    for (int i = 0; i < 16; i++) u[i] = sb[i];

#pragma unroll 14
    for (int c = 0; c < CC; c++) {
        float xa = xb0[c * TT];
        float xb = xb1[c * TT];
        unsigned long long xp = pk2(xa, xb);
        const ulonglong2* wp = (const ulonglong2*)&swd[c][0];
#pragma unroll
        for (int k = 0; k < 8; k++) {
            ulonglong2 w2 = wp[k];
            u[2 * k]     = fma2(w2.x, xp, u[2 * k]);
            u[2 * k + 1] = fma2(w2.y, xp, u[2 * k + 1]);
        }
    }

    {
        int row = ploc * 16 + tl;
        ulonglong2* st = (ulonglong2*)&sstage[row][0];
#pragma unroll
        for (int k = 0; k < 8; k++) st[k] = make_ulonglong2(u[2 * k], u[2 * k + 1]);
    }
    __syncthreads();

#pragma unroll
    for (int cc = 0; cc < 2; cc++) {
        int pl2 = w * 2 + cc;
        unsigned long long* gdst = g_U + ((size_t)(bblk * 8 + pl2) * TT + tc * 16) * 16;
#pragma unroll
        for (int j = 0; j < 4; j++) {
            int g = j * 64 + lane * 2;
            int r2 = g >> 4, col = g & 15;
            ulonglong2 v = *(const ulonglong2*)&sstage[pl2 * 16 + r2][col];
            *(ulonglong2*)&gdst[g] = v;
        }
    }
}

// ---------- Kernel B: dual-stream lagged recurrence, f32x2, fused LDS+FMA ----------
// warp = 4 pairs (8 batches) as two independent streams X (pairs 4q+s) and Y (pairs 4q+2+s).
// lane = (i, s). Per stream per step: 16x[LDS.128 -> 6 fma2] (h never persists in regs),
// 8 accumulator chains, 2 tanh2, 1 STS.128. One syncwarp covers both streams.
__global__ void __launch_bounds__(64) kB(const float* __restrict__ h0in,
                                         const float* __restrict__ Whh0,
                                         const float* __restrict__ Wih1,
                                         const float* __restrict__ Whh1,
                                         const float* __restrict__ bih1,
                                         const float* __restrict__ bhh1,
                                         const float* __restrict__ Wfc,
                                         const float* __restrict__ bfc,
                                         float* __restrict__ out) {
    __shared__ __align__(16) ulonglong2 sh[2][2][2][16];  // [warp][stream][slot s][i] = {h0pair,h1pair}

    int tid = threadIdx.x;
    int w = tid >> 5;
    int lane = tid & 31;
    int i = lane & 15;
    int s = lane >> 4;
    int q = blockIdx.x * 2 + w;  // warp id 0..511
    int pX = q * 4 + s;          // stream X pair
    int pY = q * 4 + 2 + s;      // stream Y pair

    // shared pre-scaled duplicated weight rows
    unsigned long long WH0[16], WI1[16], WH1[16];
#pragma unroll
    for (int j = 0; j < 16; j++) {
        float v0 = SCALE * Whh0[i * 16 + j];
        float v1 = SCALE * Wih1[i * 16 + j];
        float v2 = SCALE * Whh1[i * 16 + j];
        WH0[j] = pk2(v0, v0);
        WI1[j] = pk2(v1, v1);
        WH1[j] = pk2(v2, v2);
    }
    float b1f = SCALE * (bih1[i] + bhh1[i]);
    const unsigned long long B1S = pk2(b1f, b1f);

    // initial states: store h(-1) = {h0init, h1init} into the exchange arrays
    unsigned long long h1iniX, h1iniY;
    {
        int b0 = 2 * pX, b1 = b0 + 1;
        unsigned long long h0i = pk2(h0in[b0 * 16 + i], h0in[b1 * 16 + i]);
        h1iniX = pk2(h0in[BB * HH + b0 * 16 + i], h0in[BB * HH + b1 * 16 + i]);
        sh[w][0][s][i] = make_ulonglong2(h0i, h1iniX);
        b0 = 2 * pY; b1 = b0 + 1;
        h0i = pk2(h0in[b0 * 16 + i], h0in[b1 * 16 + i]);
        h1iniY = pk2(h0in[BB * HH + b0 * 16 + i], h0in[BB * HH + b1 * 16 + i]);
        sh[w][1][s][i] = make_ulonglong2(h0i, h1iniY);
    }
    __syncwarp();

    // U streams, 4-deep prefetch rings
    const unsigned long long* upX = g_U + (size_t)pX * TT * 16 + i;
    const unsigned long long* upY = g_U + (size_t)pY * TT * 16 + i;
    const unsigned long long* uendX = upX + (size_t)399 * 16;
    const unsigned long long* uendY = upY + (size_t)399 * 16;
    unsigned long long uX0 = upX[0], uX1 = upX[16], uX2 = upX[32], uX3 = upX[48];
    unsigned long long uY0 = upY[0], uY1 = upY[16], uY2 = upY[32], uY3 = upY[48];
    const unsigned long long* pfX = upX + 64;
    const unsigned long long* pfY = upY + 64;

    ulonglong2* myhX = &sh[w][0][s][i];
    ulonglong2* myhY = &sh[w][1][s][i];
    const ulonglong2* hrdX = &sh[w][0][s][0];
    const ulonglong2* hrdY = &sh[w][1][s][0];

// one stream's step: fused LDS.128 -> 6 fma2, 8 chains, 2 tanh, STS
#define KB_STEP(HRD, MYH, UC, OVR, FIRST)                                          \
    {                                                                              \
        ulonglong2 qv;                                                             \
        unsigned long long a0, a1, a2, a3, c0, c1, d0, d1;                         \
        qv = (HRD)[0];  a0 = fma2(WH0[0], qv.x, (UC));                             \
                        c0 = fma2(WI1[0], qv.x, B1S);                              \
                        d0 = fma2(WH1[0], qv.y, 0ull);                             \
        qv = (HRD)[1];  a1 = fma2(WH0[1], qv.x, 0ull);                             \
                        c1 = fma2(WI1[1], qv.x, 0ull);                             \
                        d1 = fma2(WH1[1], qv.y, 0ull);                             \
        qv = (HRD)[2];  a2 = fma2(WH0[2], qv.x, 0ull);                             \
                        c0 = fma2(WI1[2], qv.x, c0);  d0 = fma2(WH1[2], qv.y, d0); \
        qv = (HRD)[3];  a3 = fma2(WH0[3], qv.x, 0ull);                             \
                        c1 = fma2(WI1[3], qv.x, c1);  d1 = fma2(WH1[3], qv.y, d1); \
        qv = (HRD)[4];  a0 = fma2(WH0[4], qv.x, a0);                               \
                        c0 = fma2(WI1[4], qv.x, c0);  d0 = fma2(WH1[4], qv.y, d0); \
        qv = (HRD)[5];  a1 = fma2(WH0[5], qv.x, a1);                               \
                        c1 = fma2(WI1[5], qv.x, c1);  d1 = fma2(WH1[5], qv.y, d1); \
        qv = (HRD)[6];  a2 = fma2(WH0[6], qv.x, a2);                               \
                        c0 = fma2(WI1[6], qv.x, c0);  d0 = fma2(WH1[6], qv.y, d0); \
        qv = (HRD)[7];  a3 = fma2(WH0[7], qv.x, a3);                               \
                        c1 = fma2(WI1[7], qv.x, c1);  d1 = fma2(WH1[7], qv.y, d1); \
        qv = (HRD)[8];  a0 = fma2(WH0[8], qv.x, a0);                               \
                        c0 = fma2(WI1[8], qv.x, c0);  d0 = fma2(WH1[8], qv.y, d0); \
        qv = (HRD)[9];  a1 = fma2(WH0[9], qv.x, a1);                               \
                        c1 = fma2(WI1[9], qv.x, c1);  d1 = fma2(WH1[9], qv.y, d1); \
        qv = (HRD)[10]; a2 = fma2(WH0[10], qv.x, a2);                              \
                        c0 = fma2(WI1[10], qv.x, c0); d0 = fma2(WH1[10], qv.y, d0);\
        qv = (HRD)[11]; a3 = fma2(WH0[11], qv.x, a3);                              \
                        c1 = fma2(WI1[11], qv.x, c1); d1 = fma2(WH1[11], qv.y, d1);\
        qv = (HRD)[12]; a0 = fma2(WH0[12], qv.x, a0);                              \
                        c0 = fma2(WI1[12], qv.x, c0); d0 = fma2(WH1[12], qv.y, d0);\
        qv = (HRD)[13]; a1 = fma2(WH0[13], qv.x, a1);                              \
                        c1 = fma2(WI1[13], qv.x, c1); d1 = fma2(WH1[13], qv.y, d1);\
        qv = (HRD)[14]; a2 = fma2(WH0[14], qv.x, a2);                              \
                        c0 = fma2(WI1[14], qv.x, c0); d0 = fma2(WH1[14], qv.y, d0);\
        qv = (HRD)[15]; a3 = fma2(WH0[15], qv.x, a3);                              \
                        c1 = fma2(WI1[15], qv.x, c1); d1 = fma2(WH1[15], qv.y, d1);\
        unsigned long long z0 = add2(add2(a0, a1), add2(a2, a3));                  \
        unsigned long long z1 = add2(add2(c0, c1), add2(d0, d1));                  \
        unsigned long long h0n = tanh2_pre(z0);                                   \
        unsigned long long h1n = tanh2_pre(z1);                                   \
        if (FIRST) h1n = (OVR);                                                    \
        *(MYH) = make_ulonglong2(h0n, h1n);                                        \
    }

// both streams + one syncwarp; U ring regs passed by name
#define KB_SUB(UXR, UYR, FIRST)                                          \
    {                                                                    \
        const unsigned long long* qx = (pfX > uendX) ? uendX : pfX;      \
        unsigned long long tX = *qx;                                     \
        pfX += 16;                                                       \
        const unsigned long long* qy = (pfY > uendY) ? uendY : pfY;      \
        unsigned long long tY = *qy;                                     \
        pfY += 16;                                                       \
        KB_STEP(hrdX, myhX, UXR, h1iniX, FIRST);                         \
        KB_STEP(hrdY, myhY, UYR, h1iniY, FIRST);                         \
        __syncwarp();                                                    \
        UXR = tX;                                                        \
        UYR = tY;                                                        \
    }

    // 401 steps: m=0 special (h1 output overridden with init), then 100 x 4.
    KB_SUB(uX0, uY0, true);  // m=0 (ring slot 0)
#pragma unroll 1
    for (int k = 0; k < 100; k++) {
        KB_SUB(uX1, uY1, false);  // m = 4k+1
        KB_SUB(uX2, uY2, false);  // m = 4k+2
        KB_SUB(uX3, uY3, false);  // m = 4k+3
        KB_SUB(uX0, uY0, false);  // m = 4k+4
    }
#undef KB_SUB
#undef KB_STEP

    // final FC (NC=2): smem exchange holds {h0(400) junk, h1(399)}.
    // lanes i<2 -> stream X outputs (c=i); lanes 2<=i<4 -> stream Y (c=i-2).
    if (i < 4) {
        int strm = (i >> 1);
        int c = i & 1;
        int p = strm ? pY : pX;
        const ulonglong2* hr = strm ? hrdY : hrdX;
        float bf = bfc[c];
        unsigned long long acc = pk2(bf, bf);
#pragma unroll
        for (int j = 0; j < 16; j++) {
            float wv = Wfc[c * 16 + j];
            acc = fma2(pk2(wv, wv), hr[j].y, acc);
        }
        float lo, hi;
        up2(acc, lo, hi);
        out[(2 * p) * 2 + c] = lo;
        out[(2 * p + 1) * 2 + c] = hi;
    }
}

extern "C" void kernel_launch(void* const* d_in, const int* in_sizes, int n_in,
                              void* d_out, int out_size) {
    const float* x    = (const float*)d_in[0];
    const float* h0   = (const float*)d_in[1];
    const float* Wih0 = (const float*)d_in[2];
    const float* Whh0 = (const float*)d_in[3];
    const float* bih0 = (const float*)d_in[4];
    const float* bhh0 = (const float*)d_in[5];
    const float* Wih1 = (const float*)d_in[6];
    const float* Whh1 = (const float*)d_in[7];
    const float* bih1 = (const float*)d_in[8];
    const float* bhh1 = (const float*)d_in[9];
    const float* Wfc  = (const float*)d_in[10];
    const float* bfc  = (const float*)d_in[11];
    float* out = (float*)d_out;

    dim3 gA(25, 256);
    kA<<<gA, 128>>>(x, Wih0, bih0, bhh0);
    kB<<<256, 64>>>(h0, Whh0, Wih1, Whh1, bih1, bhh1, Wfc, bfc, out);
}

// round 7
// speedup vs baseline: 1.5497x; 1.5497x over previous
#include <cuda_runtime.h>

#define BB 4096
#define TT 400
#define CC 42
#define HH 16
#define SCALE 2.885390081777927f  // 2*log2(e), folded into U, recurrent weights, bias1
#define NCH 25                    // 25 chunks x 16 timesteps = 400

typedef unsigned long long u64;

// ---------- f32x2 helpers ----------
__device__ __forceinline__ u64 pk2(float lo, float hi) {
    u64 r;
    asm("mov.b64 %0, {%1, %2};" : "=l"(r) : "f"(lo), "f"(hi));
    return r;
}
__device__ __forceinline__ void up2(u64 v, float& a, float& b) {
    asm("mov.b64 {%0, %1}, %2;" : "=f"(a), "=f"(b) : "l"(v));
}
__device__ __forceinline__ u64 fma2(u64 a, u64 b, u64 c) {
    u64 d;
    asm("fma.rn.f32x2 %0, %1, %2, %3;" : "=l"(d) : "l"(a), "l"(b), "l"(c));
    return d;
}
__device__ __forceinline__ u64 add2(u64 a, u64 b) {
    u64 d;
    asm("add.rn.f32x2 %0, %1, %2;" : "=l"(d) : "l"(a), "l"(b));
    return d;
}
// tanh with pre-scaled argument: z = 2*log2(e)*x  ->  tanh(x) = 1 - 2/(1+2^z)
__device__ __forceinline__ float tanh_pre(float z) {
    float e, r;
    asm("ex2.approx.f32 %0, %1;" : "=f"(e) : "f"(z));
    asm("rcp.approx.f32 %0, %1;" : "=f"(r) : "f"(e + 1.0f));
    return fmaf(-2.0f, r, 1.0f);
}
__device__ __forceinline__ u64 tanh2_pre(u64 z) {
    float a, b;
    up2(z, a, b);
    return pk2(tanh_pre(a), tanh_pre(b));
}

// ---------- Fused producer/consumer kernel ----------
// Block = 4 pairs (8 batches), 128 threads.
//   warps 0-1: consumers — lagged dual-layer recurrence (R1/R5 math), lane=(i,s),
//              2 pairs per warp, ONE exchange per step, U read from smem.
//   warps 2-3: producers — kA inner loop (lane = 2 pairs x 16 t), writing
//              SCALE*(bias0 + Wih0 @ x_t) into smem double buffer, 16 t per chunk.
// Chunk pipeline: producers fill chunk j+1 while consumers consume chunk j;
// one uniform __syncthreads() per iteration.
__global__ void __launch_bounds__(128, 4) kFused(
    const float* __restrict__ x,
    const float* __restrict__ h0in,
    const float* __restrict__ Wih0, const float* __restrict__ Whh0,
    const float* __restrict__ bih0, const float* __restrict__ bhh0,
    const float* __restrict__ Wih1, const float* __restrict__ Whh1,
    const float* __restrict__ bih1, const float* __restrict__ bhh1,
    const float* __restrict__ Wfc, const float* __restrict__ bfc,
    float* __restrict__ out)
{
    __shared__ __align__(16) u64 sU[2][4][16][17];   // [buf][ploc][i][t] padded
    __shared__ __align__(16) u64 swd[CC][HH];        // producer weights (dup f32x2)
    __shared__ u64 sb2[HH];                          // producer bias (dup f32x2)
    __shared__ __align__(16) ulonglong2 sh[2][2][16];// exchange [cw][s][i]={h0,h1}

    int tid = threadIdx.x;
    int w = tid >> 5;
    int lane = tid & 31;
    int i = lane & 15;   // consumer: hidden unit; producer: t-slot
    int s = lane >> 4;   // pair slot

    // stage producer weights/bias (all threads help)
    for (int k = tid; k < CC * HH; k += 128) {
        int c = k >> 4, ii = k & 15;
        float wv = SCALE * Wih0[ii * CC + c];
        swd[c][ii] = pk2(wv, wv);
    }
    if (tid < HH) {
        float b = SCALE * (bih0[tid] + bhh0[tid]);
        sb2[tid] = pk2(b, b);
    }
    __syncthreads();

    const bool is_prod = (w >= 2);
    int ploc = (is_prod ? (w - 2) : w) * 2 + s;   // 0..3
    int p = blockIdx.x * 4 + ploc;                // pair 0..2047
    int b0 = 2 * p, b1 = b0 + 1;

    // ---- producer state ----
    const float* xa = x + (size_t)b0 * (CC * TT) + i;  // + t offset (i = tl)
    const float* xb = xa + CC * TT;

    // ---- consumer state ----
    u64 WH0[16], WI1[16], WH1[16];
    u64 B1S = 0, h1ini = 0;
    ulonglong2* myh = &sh[w & 1][s][i];
    const ulonglong2* hrd = &sh[w & 1][s][0];
    const u64* ub0p = &sU[0][ploc][i][0];
    const u64* ub1p = &sU[1][ploc][i][0];

    if (!is_prod) {
#pragma unroll
        for (int j = 0; j < 16; j++) {
            float v0 = SCALE * Whh0[i * 16 + j];
            float v1 = SCALE * Wih1[i * 16 + j];
            float v2 = SCALE * Whh1[i * 16 + j];
            WH0[j] = pk2(v0, v0);
            WI1[j] = pk2(v1, v1);
            WH1[j] = pk2(v2, v2);
        }
        float bf1 = SCALE * (bih1[i] + bhh1[i]);
        B1S = pk2(bf1, bf1);
        h1ini = pk2(h0in[BB * HH + b0 * 16 + i], h0in[BB * HH + b1 * 16 + i]);
        u64 h0i = pk2(h0in[b0 * 16 + i], h0in[b1 * 16 + i]);
        *myh = make_ulonglong2(h0i, h1ini);
        __syncwarp();
    }

// one recurrence step: exchange holds {h0(m-1), h1(m-2)}; produces {h0(m), h1(m-1)}
#define CSTEP(UVAL, OVRC)                                                          \
    {                                                                              \
        ulonglong2 qv;                                                             \
        u64 a0, a1, c0, c1, d0, d1;                                                \
        qv = hrd[0];  a0 = fma2(WH0[0], qv.x, (UVAL));                             \
                      c0 = fma2(WI1[0], qv.x, B1S);                                \
                      d0 = fma2(WH1[0], qv.y, 0ull);                               \
        qv = hrd[1];  a1 = fma2(WH0[1], qv.x, 0ull);                               \
                      c1 = fma2(WI1[1], qv.x, 0ull);                               \
                      d1 = fma2(WH1[1], qv.y, 0ull);                               \
        qv = hrd[2];  a0 = fma2(WH0[2], qv.x, a0);                                 \
                      c0 = fma2(WI1[2], qv.x, c0); d0 = fma2(WH1[2], qv.y, d0);    \
        qv = hrd[3];  a1 = fma2(WH0[3], qv.x, a1);                                 \
                      c1 = fma2(WI1[3], qv.x, c1); d1 = fma2(WH1[3], qv.y, d1);    \
        qv = hrd[4];  a0 = fma2(WH0[4], qv.x, a0);                                 \
                      c0 = fma2(WI1[4], qv.x, c0); d0 = fma2(WH1[4], qv.y, d0);    \
        qv = hrd[5];  a1 = fma2(WH0[5], qv.x, a1);                                 \
                      c1 = fma2(WI1[5], qv.x, c1); d1 = fma2(WH1[5], qv.y, d1);    \
        qv = hrd[6];  a0 = fma2(WH0[6], qv.x, a0);                                 \
                      c0 = fma2(WI1[6], qv.x, c0); d0 = fma2(WH1[6], qv.y, d0);    \
        qv = hrd[7];  a1 = fma2(WH0[7], qv.x, a1);                                 \
                      c1 = fma2(WI1[7], qv.x, c1); d1 = fma2(WH1[7], qv.y, d1);    \
        qv = hrd[8];  a0 = fma2(WH0[8], qv.x, a0);                                 \
                      c0 = fma2(WI1[8], qv.x, c0); d0 = fma2(WH1[8], qv.y, d0);    \
        qv = hrd[9];  a1 = fma2(WH0[9], qv.x, a1);                                 \
                      c1 = fma2(WI1[9], qv.x, c1); d1 = fma2(WH1[9], qv.y, d1);    \
        qv = hrd[10]; a0 = fma2(WH0[10], qv.x, a0);                                \
                      c0 = fma2(WI1[10], qv.x, c0); d0 = fma2(WH1[10], qv.y, d0);  \
        qv = hrd[11]; a1 = fma2(WH0[11], qv.x, a1);                                \
                      c1 = fma2(WI1[11], qv.x, c1); d1 = fma2(WH1[11], qv.y, d1);  \
        qv = hrd[12]; a0 = fma2(WH0[12], qv.x, a0);                                \
                      c0 = fma2(WI1[12], qv.x, c0); d0 = fma2(WH1[12], qv.y, d0);  \
        qv = hrd[13]; a1 = fma2(WH0[13], qv.x, a1);                                \
                      c1 = fma2(WI1[13], qv.x, c1); d1 = fma2(WH1[13], qv.y, d1);  \
        qv = hrd[14]; a0 = fma2(WH0[14], qv.x, a0);                                \
                      c0 = fma2(WI1[14], qv.x, c0); d0 = fma2(WH1[14], qv.y, d0);  \
        qv = hrd[15]; a1 = fma2(WH0[15], qv.x, a1);                                \
                      c1 = fma2(WI1[15], qv.x, c1); d1 = fma2(WH1[15], qv.y, d1);  \
        u64 h0n = tanh2_pre(add2(a0, a1));                                         \
        u64 h1n = tanh2_pre(add2(add2(c0, c1), add2(d0, d1)));                     \
        if (OVRC) h1n = h1ini;                                                     \
        *myh = make_ulonglong2(h0n, h1n);                                          \
        __syncwarp();                                                              \
    }

    // ---- main pipeline: iteration j: producers fill chunk j; consumers eat j-1 ----
    for (int j = 0; j < NCH; j++) {
        if (is_prod) {
            u64 u[16];
#pragma unroll
            for (int ii = 0; ii < 16; ii++) u[ii] = sb2[ii];
            const float* pa = xa + j * 16;
            const float* pb = xb + j * 16;
#pragma unroll 14
            for (int c = 0; c < CC; c++) {
                u64 xp = pk2(pa[c * TT], pb[c * TT]);
                const ulonglong2* wp = (const ulonglong2*)&swd[c][0];
#pragma unroll
                for (int k8 = 0; k8 < 8; k8++) {
                    ulonglong2 w2 = wp[k8];
                    u[2 * k8] = fma2(w2.x, xp, u[2 * k8]);
                    u[2 * k8 + 1] = fma2(w2.y, xp, u[2 * k8 + 1]);
                }
            }
            u64* dst = &sU[j & 1][ploc][0][i];  // i = tl
#pragma unroll
            for (int ii = 0; ii < 16; ii++) dst[ii * 17] = u[ii];
        } else if (j >= 1) {
            int kk = j - 1;
            const u64* ur = (kk & 1) ? ub1p : ub0p;
            if (kk == 0) {
                // chunk 0: step 0 overrides h1 output with the initial state
                {
                    u64 uval = ur[0];
                    CSTEP(uval, true);
                }
#pragma unroll
                for (int stp = 1; stp < 16; stp++) {
                    u64 uval = ur[stp];
                    CSTEP(uval, false);
                }
            } else {
#pragma unroll
                for (int stp = 0; stp < 16; stp++) {
                    u64 uval = ur[stp];
                    CSTEP(uval, false);
                }
            }
        }
        __syncthreads();
    }

    if (!is_prod) {
        // last chunk (24), no barrier needed afterwards
        const u64* ur = ub0p;  // 24 & 1 == 0
#pragma unroll
        for (int stp = 0; stp < 16; stp++) {
            u64 uval = ur[stp];
            CSTEP(uval, false);
        }
        // exchange now holds {h0(399), h1(398)} — final step computes h1(399)
        {
            ulonglong2 qv;
            u64 c0, c1, d0, d1;
            qv = hrd[0];  c0 = fma2(WI1[0], qv.x, B1S);  d0 = fma2(WH1[0], qv.y, 0ull);
            qv = hrd[1];  c1 = fma2(WI1[1], qv.x, 0ull); d1 = fma2(WH1[1], qv.y, 0ull);
            qv = hrd[2];  c0 = fma2(WI1[2], qv.x, c0);   d0 = fma2(WH1[2], qv.y, d0);
            qv = hrd[3];  c1 = fma2(WI1[3], qv.x, c1);   d1 = fma2(WH1[3], qv.y, d1);
            qv = hrd[4];  c0 = fma2(WI1[4], qv.x, c0);   d0 = fma2(WH1[4], qv.y, d0);
            qv = hrd[5];  c1 = fma2(WI1[5], qv.x, c1);   d1 = fma2(WH1[5], qv.y, d1);
            qv = hrd[6];  c0 = fma2(WI1[6], qv.x, c0);   d0 = fma2(WH1[6], qv.y, d0);
            qv = hrd[7];  c1 = fma2(WI1[7], qv.x, c1);   d1 = fma2(WH1[7], qv.y, d1);
            qv = hrd[8];  c0 = fma2(WI1[8], qv.x, c0);   d0 = fma2(WH1[8], qv.y, d0);
            qv = hrd[9];  c1 = fma2(WI1[9], qv.x, c1);   d1 = fma2(WH1[9], qv.y, d1);
            qv = hrd[10]; c0 = fma2(WI1[10], qv.x, c0);  d0 = fma2(WH1[10], qv.y, d0);
            qv = hrd[11]; c1 = fma2(WI1[11], qv.x, c1);  d1 = fma2(WH1[11], qv.y, d1);
            qv = hrd[12]; c0 = fma2(WI1[12], qv.x, c0);  d0 = fma2(WH1[12], qv.y, d0);
            qv = hrd[13]; c1 = fma2(WI1[13], qv.x, c1);  d1 = fma2(WH1[13], qv.y, d1);
            qv = hrd[14]; c0 = fma2(WI1[14], qv.x, c0);  d0 = fma2(WH1[14], qv.y, d0);
            qv = hrd[15]; c1 = fma2(WI1[15], qv.x, c1);  d1 = fma2(WH1[15], qv.y, d1);
            u64 h1n = tanh2_pre(add2(add2(c0, c1), add2(d0, d1)));
            *myh = make_ulonglong2(0ull, h1n);
            __syncwarp();
        }
        // final FC (NC=2): out[b][c] = bfc[c] + sum_j Wfc[c][j] * h1(399)[j]
        if (i < 2) {
            float bfv = bfc[i];
            u64 acc = pk2(bfv, bfv);
#pragma unroll
            for (int j = 0; j < 16; j++) {
                float wv = Wfc[i * 16 + j];
                acc = fma2(pk2(wv, wv), hrd[j].y, acc);
            }
            float lo, hi;
            up2(acc, lo, hi);
            out[b0 * 2 + i] = lo;
            out[b1 * 2 + i] = hi;
        }
    }
#undef CSTEP
}

extern "C" void kernel_launch(void* const* d_in, const int* in_sizes, int n_in,
                              void* d_out, int out_size) {
    const float* x    = (const float*)d_in[0];
    const float* h0   = (const float*)d_in[1];
    const float* Wih0 = (const float*)d_in[2];
    const float* Whh0 = (const float*)d_in[3];
    const float* bih0 = (const float*)d_in[4];
    const float* bhh0 = (const float*)d_in[5];
    const float* Wih1 = (const float*)d_in[6];
    const float* Whh1 = (const float*)d_in[7];
    const float* bih1 = (const float*)d_in[8];
    const float* bhh1 = (const float*)d_in[9];
    const float* Wfc  = (const float*)d_in[10];
    const float* bfc  = (const float*)d_in[11];
    float* out = (float*)d_out;

    kFused<<<512, 128>>>(x, h0, Wih0, Whh0, bih0, bhh0,
                         Wih1, Whh1, bih1, bhh1, Wfc, bfc, out);
}